// round 3
// baseline (speedup 1.0000x reference)
#include <cuda_runtime.h>

// Problem constants
#define BATCH 4
#define SEQ   2048
#define EMB   1024
#define HDIM  1024

// GEMM tiling
#define BM 128
#define BN 128
#define BK 16
#define TM 8
#define TN 8
#define NTHREADS 256

// Scratch (static device allocations; no runtime allocs allowed)
__device__ float g_qkv[3][BATCH * SEQ * EMB];   // Q, K, V  : 3 x 32 MB
__device__ float g_p[(size_t)BATCH * SEQ * SEQ]; // attn mat : 64 MB

// ---------------------------------------------------------------------------
// Kernel 1: QKV projection.  out[m][e] = sum_h x[m][h] * W[e][h] + bias[e]
// NT GEMM: both operands K-contiguous. grid.z in {0,1,2} selects Q/K/V.
// ---------------------------------------------------------------------------
__global__ void __launch_bounds__(NTHREADS)
qkv_kernel(const float* __restrict__ x,
           const float* __restrict__ w0, const float* __restrict__ bias0,
           const float* __restrict__ w1, const float* __restrict__ bias1,
           const float* __restrict__ w2, const float* __restrict__ bias2)
{
    __shared__ float As[BK][BM];
    __shared__ float Bs[BK][BN];

    const int which = blockIdx.z;
    const float* W    = (which == 0) ? w0 : (which == 1) ? w1 : w2;
    const float* bias = (which == 0) ? bias0 : (which == 1) ? bias1 : bias2;
    float* out = g_qkv[which];

    const int m0 = blockIdx.y * BM;
    const int n0 = blockIdx.x * BN;
    const int tid = threadIdx.x;
    const int tx = tid & 15;
    const int ty = tid >> 4;
    const int lrow = tid >> 2;   // 0..63
    const int lc4  = tid & 3;    // 0..3

    float acc[TM][TN];
#pragma unroll
    for (int i = 0; i < TM; i++)
#pragma unroll
        for (int j = 0; j < TN; j++) acc[i][j] = 0.f;

    for (int k0 = 0; k0 < HDIM; k0 += BK) {
#pragma unroll
        for (int r = 0; r < 2; r++) {
            const int row = lrow + r * 64;
            float4 av = *(const float4*)(x + (size_t)(m0 + row) * HDIM + k0 + lc4 * 4);
            float4 bv = *(const float4*)(W + (size_t)(n0 + row) * HDIM + k0 + lc4 * 4);
            As[lc4 * 4 + 0][row] = av.x;
            As[lc4 * 4 + 1][row] = av.y;
            As[lc4 * 4 + 2][row] = av.z;
            As[lc4 * 4 + 3][row] = av.w;
            Bs[lc4 * 4 + 0][row] = bv.x;
            Bs[lc4 * 4 + 1][row] = bv.y;
            Bs[lc4 * 4 + 2][row] = bv.z;
            Bs[lc4 * 4 + 3][row] = bv.w;
        }
        __syncthreads();
#pragma unroll
        for (int kk = 0; kk < BK; kk++) {
            float4 a0 = *(const float4*)&As[kk][ty * TM];
            float4 a1 = *(const float4*)&As[kk][ty * TM + 4];
            float4 b0 = *(const float4*)&Bs[kk][tx * TN];
            float4 b1 = *(const float4*)&Bs[kk][tx * TN + 4];
            float a[TM] = {a0.x, a0.y, a0.z, a0.w, a1.x, a1.y, a1.z, a1.w};
            float b[TN] = {b0.x, b0.y, b0.z, b0.w, b1.x, b1.y, b1.z, b1.w};
#pragma unroll
            for (int i = 0; i < TM; i++)
#pragma unroll
                for (int j = 0; j < TN; j++)
                    acc[i][j] += a[i] * b[j];
        }
        __syncthreads();
    }

    float bb[TN];
#pragma unroll
    for (int j = 0; j < TN; j++) bb[j] = bias[n0 + tx * TN + j];

#pragma unroll
    for (int i = 0; i < TM; i++) {
        const int m = m0 + ty * TM + i;
        float* o = out + (size_t)m * EMB + n0 + tx * TN;
        float4 r0 = {acc[i][0] + bb[0], acc[i][1] + bb[1], acc[i][2] + bb[2], acc[i][3] + bb[3]};
        float4 r1 = {acc[i][4] + bb[4], acc[i][5] + bb[5], acc[i][6] + bb[6], acc[i][7] + bb[7]};
        *(float4*)(o)     = r0;
        *(float4*)(o + 4) = r1;
    }
}

// ---------------------------------------------------------------------------
// Kernel 2: masked scores.  P[b][q][n] = (Q[b][q] . K[b][n]) / 32
// Only lower-triangular (nt <= qt) tiles computed; others skipped entirely.
// ---------------------------------------------------------------------------
__global__ void __launch_bounds__(NTHREADS)
scores_kernel()
{
    const int qt = blockIdx.y;
    const int nt = blockIdx.x;
    if (nt > qt) return;
    const int b = blockIdx.z;

    const float* Q  = g_qkv[0] + (size_t)b * SEQ * EMB;
    const float* Km = g_qkv[1] + (size_t)b * SEQ * EMB;
    float* P = g_p + (size_t)b * SEQ * SEQ;

    __shared__ float As[BK][BM];
    __shared__ float Bs[BK][BN];

    const int m0 = qt * BM;
    const int n0 = nt * BN;
    const int tid = threadIdx.x;
    const int tx = tid & 15;
    const int ty = tid >> 4;
    const int lrow = tid >> 2;
    const int lc4  = tid & 3;

    float acc[TM][TN];
#pragma unroll
    for (int i = 0; i < TM; i++)
#pragma unroll
        for (int j = 0; j < TN; j++) acc[i][j] = 0.f;

    for (int k0 = 0; k0 < EMB; k0 += BK) {
#pragma unroll
        for (int r = 0; r < 2; r++) {
            const int row = lrow + r * 64;
            float4 av = *(const float4*)(Q  + (size_t)(m0 + row) * EMB + k0 + lc4 * 4);
            float4 bv = *(const float4*)(Km + (size_t)(n0 + row) * EMB + k0 + lc4 * 4);
            As[lc4 * 4 + 0][row] = av.x;
            As[lc4 * 4 + 1][row] = av.y;
            As[lc4 * 4 + 2][row] = av.z;
            As[lc4 * 4 + 3][row] = av.w;
            Bs[lc4 * 4 + 0][row] = bv.x;
            Bs[lc4 * 4 + 1][row] = bv.y;
            Bs[lc4 * 4 + 2][row] = bv.z;
            Bs[lc4 * 4 + 3][row] = bv.w;
        }
        __syncthreads();
#pragma unroll
        for (int kk = 0; kk < BK; kk++) {
            float4 a0 = *(const float4*)&As[kk][ty * TM];
            float4 a1 = *(const float4*)&As[kk][ty * TM + 4];
            float4 b0 = *(const float4*)&Bs[kk][tx * TN];
            float4 b1 = *(const float4*)&Bs[kk][tx * TN + 4];
            float a[TM] = {a0.x, a0.y, a0.z, a0.w, a1.x, a1.y, a1.z, a1.w};
            float b[TN] = {b0.x, b0.y, b0.z, b0.w, b1.x, b1.y, b1.z, b1.w};
#pragma unroll
            for (int i = 0; i < TM; i++)
#pragma unroll
                for (int j = 0; j < TN; j++)
                    acc[i][j] += a[i] * b[j];
        }
        __syncthreads();
    }

    const float scale = 0.03125f;  // 1/sqrt(1024)
#pragma unroll
    for (int i = 0; i < TM; i++) {
        const int m = m0 + ty * TM + i;
        float* o = P + (size_t)m * SEQ + n0 + tx * TN;
        float4 r0 = {acc[i][0] * scale, acc[i][1] * scale, acc[i][2] * scale, acc[i][3] * scale};
        float4 r1 = {acc[i][4] * scale, acc[i][5] * scale, acc[i][6] * scale, acc[i][7] * scale};
        *(float4*)(o)     = r0;
        *(float4*)(o + 4) = r1;
    }
}

// ---------------------------------------------------------------------------
// Kernel 3: row softmax over cols [0..q], exact zeros for cols (q..SEQ).
// One block per (b, q) row; row cached in smem.
// ---------------------------------------------------------------------------
__global__ void __launch_bounds__(NTHREADS)
softmax_kernel()
{
    __shared__ float buf[SEQ];
    __shared__ float red[8];

    const int q = blockIdx.x & (SEQ - 1);
    const int b = blockIdx.x >> 11;
    float* row = g_p + ((size_t)b * SEQ + q) * SEQ;
    const int n = q + 1;
    const int tid = threadIdx.x;
    const int lane = tid & 31;
    const int wid = tid >> 5;

    float lmax = -1e30f;
    for (int i = tid; i < n; i += NTHREADS) {
        float v = row[i];
        buf[i] = v;
        lmax = fmaxf(lmax, v);
    }
#pragma unroll
    for (int off = 16; off; off >>= 1)
        lmax = fmaxf(lmax, __shfl_xor_sync(0xffffffffu, lmax, off));
    if (lane == 0) red[wid] = lmax;
    __syncthreads();
    float gmax = red[0];
#pragma unroll
    for (int w = 1; w < 8; w++) gmax = fmaxf(gmax, red[w]);
    __syncthreads();

    float lsum = 0.f;
    for (int i = tid; i < n; i += NTHREADS) {
        float e = __expf(buf[i] - gmax);
        buf[i] = e;
        lsum += e;
    }
#pragma unroll
    for (int off = 16; off; off >>= 1)
        lsum += __shfl_xor_sync(0xffffffffu, lsum, off);
    if (lane == 0) red[wid] = lsum;
    __syncthreads();
    float gsum = red[0];
#pragma unroll
    for (int w = 1; w < 8; w++) gsum += red[w];

    const float inv = 1.f / gsum;
    for (int i = tid; i < n; i += NTHREADS) row[i] = buf[i] * inv;
    for (int i = n + tid; i < SEQ; i += NTHREADS) row[i] = 0.f;
}

// ---------------------------------------------------------------------------
// Kernel 4: O = P @ V.  NN GEMM, K-extent truncated to (mt+1)*BM (causal:
// P is exactly zero beyond each row's diagonal).
// ---------------------------------------------------------------------------
__global__ void __launch_bounds__(NTHREADS)
pv_kernel(float* __restrict__ out)
{
    const int b  = blockIdx.z;
    const int mt = blockIdx.y;
    const int e0 = blockIdx.x * BN;

    const float* P = g_p + (size_t)b * SEQ * SEQ;
    const float* V = g_qkv[2] + (size_t)b * SEQ * EMB;

    __shared__ float As[BK][BM];
    __shared__ float Bs[BK][BN];

    const int m0 = mt * BM;
    const int klen = (mt + 1) * BM;
    const int tid = threadIdx.x;
    const int tx = tid & 15;
    const int ty = tid >> 4;
    const int lrow = tid >> 2;   // A loader: 0..63
    const int lc4  = tid & 3;
    const int brow = tid >> 5;   // B loader: 0..7
    const int bc   = tid & 31;

    float acc[TM][TN];
#pragma unroll
    for (int i = 0; i < TM; i++)
#pragma unroll
        for (int j = 0; j < TN; j++) acc[i][j] = 0.f;

    for (int k0 = 0; k0 < klen; k0 += BK) {
        // A tile: P[m0+row][k0..k0+15], transpose into As[k][m]
#pragma unroll
        for (int r = 0; r < 2; r++) {
            const int row = lrow + r * 64;
            float4 av = *(const float4*)(P + (size_t)(m0 + row) * SEQ + k0 + lc4 * 4);
            As[lc4 * 4 + 0][row] = av.x;
            As[lc4 * 4 + 1][row] = av.y;
            As[lc4 * 4 + 2][row] = av.z;
            As[lc4 * 4 + 3][row] = av.w;
        }
        // B tile: V[k0+kr][e0..e0+127], natural layout
#pragma unroll
        for (int r = 0; r < 2; r++) {
            const int kr = brow + r * 8;
            float4 bv = *(const float4*)(V + (size_t)(k0 + kr) * EMB + e0 + bc * 4);
            *(float4*)&Bs[kr][bc * 4] = bv;
        }
        __syncthreads();
#pragma unroll
        for (int kk = 0; kk < BK; kk++) {
            float4 a0 = *(const float4*)&As[kk][ty * TM];
            float4 a1 = *(const float4*)&As[kk][ty * TM + 4];
            float4 b0 = *(const float4*)&Bs[kk][tx * TN];
            float4 b1 = *(const float4*)&Bs[kk][tx * TN + 4];
            float a[TM] = {a0.x, a0.y, a0.z, a0.w, a1.x, a1.y, a1.z, a1.w};
            float b[TN] = {b0.x, b0.y, b0.z, b0.w, b1.x, b1.y, b1.z, b1.w};
#pragma unroll
            for (int i = 0; i < TM; i++)
#pragma unroll
                for (int j = 0; j < TN; j++)
                    acc[i][j] += a[i] * b[j];
        }
        __syncthreads();
    }

#pragma unroll
    for (int i = 0; i < TM; i++) {
        const int m = m0 + ty * TM + i;
        float* o = out + ((size_t)b * SEQ + m) * EMB + e0 + tx * TN;
        float4 r0 = {acc[i][0], acc[i][1], acc[i][2], acc[i][3]};
        float4 r1 = {acc[i][4], acc[i][5], acc[i][6], acc[i][7]};
        *(float4*)(o)     = r0;
        *(float4*)(o + 4) = r1;
    }
}

// ---------------------------------------------------------------------------
extern "C" void kernel_launch(void* const* d_in, const int* in_sizes, int n_in,
                              void* d_out, int out_size)
{
    const float* xs = (const float*)d_in[0];
    const float* wq = (const float*)d_in[1];
    const float* bq = (const float*)d_in[2];
    const float* wk = (const float*)d_in[3];
    const float* bk = (const float*)d_in[4];
    const float* wv = (const float*)d_in[5];
    const float* bv = (const float*)d_in[6];
    float* out = (float*)d_out;

    dim3 gqkv(EMB / BN, (BATCH * SEQ) / BM, 3);          // (8, 64, 3)
    qkv_kernel<<<gqkv, NTHREADS>>>(xs, wq, bq, wk, bk, wv, bv);

    dim3 gsc(SEQ / BN, SEQ / BM, BATCH);                 // (16, 16, 4)
    scores_kernel<<<gsc, NTHREADS>>>();

    softmax_kernel<<<BATCH * SEQ, NTHREADS>>>();         // 8192 blocks

    dim3 gpv(EMB / BN, SEQ / BM, BATCH);                 // (8, 16, 4)
    pv_kernel<<<gpv, NTHREADS>>>(out);
}

// round 5
// speedup vs baseline: 3.0944x; 3.0944x over previous
#include <cuda_runtime.h>
#include <cstdint>

// Problem constants
#define BATCH 4
#define SEQ   2048
#define EMB   1024
#define HDIM  1024

// Tiling
#define BM 128
#define BN 128
#define BK 16
#define NTHREADS 256

#define AS_STRIDE 20    // 16 + 4 pad (floats) -> conflict-free frag loads
#define VS_STRIDE 136   // 128 + 8 pad (floats) -> conflict-free frag loads

// Scratch (static device allocations; no runtime allocs allowed)
__device__ float g_qkv[3][(size_t)BATCH * SEQ * EMB];   // Q, K, V
__device__ float g_p[(size_t)BATCH * SEQ * SEQ];         // attention matrix

// ---------------------------------------------------------------------------
// PTX helpers
// ---------------------------------------------------------------------------
__device__ __forceinline__ uint32_t f2tf(float x) {
    uint32_t r;
    asm("cvt.rna.tf32.f32 %0, %1;" : "=r"(r) : "f"(x));
    return r;
}

__device__ __forceinline__ void mma8(float* c, const uint32_t* a,
                                     uint32_t b0, uint32_t b1) {
    asm volatile(
        "mma.sync.aligned.m16n8k8.row.col.f32.tf32.tf32.f32 "
        "{%0,%1,%2,%3}, {%4,%5,%6,%7}, {%8,%9}, {%0,%1,%2,%3};"
        : "+f"(c[0]), "+f"(c[1]), "+f"(c[2]), "+f"(c[3])
        : "r"(a[0]), "r"(a[1]), "r"(a[2]), "r"(a[3]), "r"(b0), "r"(b1));
}

__device__ __forceinline__ void cp16(uint32_t dst, const float* src) {
    asm volatile("cp.async.ca.shared.global [%0], [%1], 16;" :: "r"(dst), "l"(src));
}
__device__ __forceinline__ void cp_commit() { asm volatile("cp.async.commit_group;"); }
template <int N>
__device__ __forceinline__ void cp_wait() { asm volatile("cp.async.wait_group %0;" :: "n"(N)); }

// ---------------------------------------------------------------------------
// Kernel 1: QKV projection. out[m][e] = sum_h x[m][h]*W[e][h] + bias[e]
// NT GEMM (both operands K-contiguous). grid.z selects Q/K/V.
// ---------------------------------------------------------------------------
__global__ void __launch_bounds__(NTHREADS, 2)
qkv_kernel(const float* __restrict__ x,
           const float* __restrict__ w0, const float* __restrict__ bi0,
           const float* __restrict__ w1, const float* __restrict__ bi1,
           const float* __restrict__ w2, const float* __restrict__ bi2)
{
    __shared__ float As[2][BM * AS_STRIDE];
    __shared__ float Bs[2][BN * AS_STRIDE];

    const int which = blockIdx.z;
    const float* W    = (which == 0) ? w0 : (which == 1) ? w1 : w2;
    const float* bias = (which == 0) ? bi0 : (which == 1) ? bi1 : bi2;
    float* out = g_qkv[which];

    const int m0 = blockIdx.y * BM, n0 = blockIdx.x * BN;
    const int tid = threadIdx.x;
    const int warp = tid >> 5, lane = tid & 31;
    const int wm = warp & 1, wn = warp >> 1;
    const int g = lane >> 2, tig = lane & 3;

    // loaders: thread -> (row tid>>2 and +64), float4 column (tid&3)
    const int ar = tid >> 2, ac = (tid & 3) * 4;
    const float* ag = x + (size_t)(m0 + ar) * HDIM + ac;
    const float* bg = W + (size_t)(n0 + ar) * HDIM + ac;
    const uint32_t asw = (uint32_t)__cvta_generic_to_shared(&As[0][0]) + (ar * AS_STRIDE + ac) * 4;
    const uint32_t bsw = (uint32_t)__cvta_generic_to_shared(&Bs[0][0]) + (ar * AS_STRIDE + ac) * 4;
    const uint32_t BUF = BM * AS_STRIDE * 4;
    const uint32_t ROWS64 = 64 * AS_STRIDE * 4;

    float acc[4][4][4];
#pragma unroll
    for (int i = 0; i < 4; i++)
#pragma unroll
        for (int j = 0; j < 4; j++)
#pragma unroll
            for (int k = 0; k < 4; k++) acc[i][j][k] = 0.f;

    // prefetch tile 0
    cp16(asw, ag);              cp16(asw + ROWS64, ag + (size_t)64 * HDIM);
    cp16(bsw, bg);              cp16(bsw + ROWS64, bg + (size_t)64 * HDIM);
    cp_commit();

    const int T = HDIM / BK;
    for (int t = 0; t < T; ++t) {
        if (t + 1 < T) {
            const int nb = (t + 1) & 1;
            const float* a2 = ag + (t + 1) * BK;
            const float* b2 = bg + (t + 1) * BK;
            cp16(asw + nb * BUF, a2);           cp16(asw + nb * BUF + ROWS64, a2 + (size_t)64 * HDIM);
            cp16(bsw + nb * BUF, b2);           cp16(bsw + nb * BUF + ROWS64, b2 + (size_t)64 * HDIM);
            cp_commit();
            cp_wait<1>();
        } else {
            cp_wait<0>();
        }
        __syncthreads();

        const float* Ab = &As[t & 1][0];
        const float* Bb = &Bs[t & 1][0];
#pragma unroll
        for (int kk = 0; kk < 2; ++kk) {
            uint32_t a[4][4];
#pragma unroll
            for (int mi = 0; mi < 4; ++mi) {
                const float* p = Ab + (wm * 64 + mi * 16 + g) * AS_STRIDE + kk * 8 + tig;
                a[mi][0] = f2tf(p[0]);
                a[mi][2] = f2tf(p[4]);
                a[mi][1] = f2tf(p[8 * AS_STRIDE]);
                a[mi][3] = f2tf(p[8 * AS_STRIDE + 4]);
            }
#pragma unroll
            for (int ni = 0; ni < 4; ++ni) {
                const float* q = Bb + (wn * 32 + ni * 8 + g) * AS_STRIDE + kk * 8 + tig;
                uint32_t bf0 = f2tf(q[0]), bf1 = f2tf(q[4]);
#pragma unroll
                for (int mi = 0; mi < 4; ++mi) mma8(acc[mi][ni], a[mi], bf0, bf1);
            }
        }
        __syncthreads();
    }

    // epilogue: +bias
#pragma unroll
    for (int mi = 0; mi < 4; ++mi) {
        const int row = m0 + wm * 64 + mi * 16 + g;
#pragma unroll
        for (int ni = 0; ni < 4; ++ni) {
            const int col = n0 + wn * 32 + ni * 8 + 2 * tig;
            const float b0v = bias[col], b1v = bias[col + 1];
            float2 r0 = {acc[mi][ni][0] + b0v, acc[mi][ni][1] + b1v};
            float2 r1 = {acc[mi][ni][2] + b0v, acc[mi][ni][3] + b1v};
            *(float2*)(out + (size_t)row * EMB + col)       = r0;
            *(float2*)(out + (size_t)(row + 8) * EMB + col) = r1;
        }
    }
}

// ---------------------------------------------------------------------------
// Kernel 2: scores. P[b][q][n] = (Q[b][q].K[b][n]) / 32
// Only lower-triangular tiles; upper-in-diagonal garbage never read by softmax.
// ---------------------------------------------------------------------------
__global__ void __launch_bounds__(NTHREADS, 2)
scores_kernel()
{
    const int qt = blockIdx.y, nt = blockIdx.x;
    if (nt > qt) return;
    const int b = blockIdx.z;

    __shared__ float As[2][BM * AS_STRIDE];
    __shared__ float Bs[2][BN * AS_STRIDE];

    const float* Q  = g_qkv[0] + (size_t)b * SEQ * EMB;
    const float* Km = g_qkv[1] + (size_t)b * SEQ * EMB;
    float* P = g_p + (size_t)b * SEQ * SEQ;

    const int m0 = qt * BM, n0 = nt * BN;
    const int tid = threadIdx.x;
    const int warp = tid >> 5, lane = tid & 31;
    const int wm = warp & 1, wn = warp >> 1;
    const int g = lane >> 2, tig = lane & 3;

    const int ar = tid >> 2, ac = (tid & 3) * 4;
    const float* ag = Q  + (size_t)(m0 + ar) * EMB + ac;
    const float* bg = Km + (size_t)(n0 + ar) * EMB + ac;
    const uint32_t asw = (uint32_t)__cvta_generic_to_shared(&As[0][0]) + (ar * AS_STRIDE + ac) * 4;
    const uint32_t bsw = (uint32_t)__cvta_generic_to_shared(&Bs[0][0]) + (ar * AS_STRIDE + ac) * 4;
    const uint32_t BUF = BM * AS_STRIDE * 4;
    const uint32_t ROWS64 = 64 * AS_STRIDE * 4;

    float acc[4][4][4];
#pragma unroll
    for (int i = 0; i < 4; i++)
#pragma unroll
        for (int j = 0; j < 4; j++)
#pragma unroll
            for (int k = 0; k < 4; k++) acc[i][j][k] = 0.f;

    cp16(asw, ag);              cp16(asw + ROWS64, ag + (size_t)64 * EMB);
    cp16(bsw, bg);              cp16(bsw + ROWS64, bg + (size_t)64 * EMB);
    cp_commit();

    const int T = EMB / BK;
    for (int t = 0; t < T; ++t) {
        if (t + 1 < T) {
            const int nb = (t + 1) & 1;
            const float* a2 = ag + (t + 1) * BK;
            const float* b2 = bg + (t + 1) * BK;
            cp16(asw + nb * BUF, a2);           cp16(asw + nb * BUF + ROWS64, a2 + (size_t)64 * EMB);
            cp16(bsw + nb * BUF, b2);           cp16(bsw + nb * BUF + ROWS64, b2 + (size_t)64 * EMB);
            cp_commit();
            cp_wait<1>();
        } else {
            cp_wait<0>();
        }
        __syncthreads();

        const float* Ab = &As[t & 1][0];
        const float* Bb = &Bs[t & 1][0];
#pragma unroll
        for (int kk = 0; kk < 2; ++kk) {
            uint32_t a[4][4];
#pragma unroll
            for (int mi = 0; mi < 4; ++mi) {
                const float* p = Ab + (wm * 64 + mi * 16 + g) * AS_STRIDE + kk * 8 + tig;
                a[mi][0] = f2tf(p[0]);
                a[mi][2] = f2tf(p[4]);
                a[mi][1] = f2tf(p[8 * AS_STRIDE]);
                a[mi][3] = f2tf(p[8 * AS_STRIDE + 4]);
            }
#pragma unroll
            for (int ni = 0; ni < 4; ++ni) {
                const float* q = Bb + (wn * 32 + ni * 8 + g) * AS_STRIDE + kk * 8 + tig;
                uint32_t bf0 = f2tf(q[0]), bf1 = f2tf(q[4]);
#pragma unroll
                for (int mi = 0; mi < 4; ++mi) mma8(acc[mi][ni], a[mi], bf0, bf1);
            }
        }
        __syncthreads();
    }

    const float scale = 0.03125f;  // 1/sqrt(1024)
#pragma unroll
    for (int mi = 0; mi < 4; ++mi) {
        const int row = m0 + wm * 64 + mi * 16 + g;
#pragma unroll
        for (int ni = 0; ni < 4; ++ni) {
            const int col = n0 + wn * 32 + ni * 8 + 2 * tig;
            float2 r0 = {acc[mi][ni][0] * scale, acc[mi][ni][1] * scale};
            float2 r1 = {acc[mi][ni][2] * scale, acc[mi][ni][3] * scale};
            *(float2*)(P + (size_t)row * SEQ + col)       = r0;
            *(float2*)(P + (size_t)(row + 8) * SEQ + col) = r1;
        }
    }
}

// ---------------------------------------------------------------------------
// Kernel 3: row softmax over [0..q], exact zeros above diagonal.
// ---------------------------------------------------------------------------
__global__ void __launch_bounds__(NTHREADS)
softmax_kernel()
{
    __shared__ float buf[SEQ];
    __shared__ float red[8];

    const int q = blockIdx.x & (SEQ - 1);
    const int b = blockIdx.x >> 11;
    float* row = g_p + ((size_t)b * SEQ + q) * SEQ;
    const int n = q + 1;
    const int tid = threadIdx.x;
    const int lane = tid & 31;
    const int wid = tid >> 5;

    float lmax = -1e30f;
    for (int i = tid; i < n; i += NTHREADS) {
        float v = row[i];
        buf[i] = v;
        lmax = fmaxf(lmax, v);
    }
#pragma unroll
    for (int off = 16; off; off >>= 1)
        lmax = fmaxf(lmax, __shfl_xor_sync(0xffffffffu, lmax, off));
    if (lane == 0) red[wid] = lmax;
    __syncthreads();
    float gmax = red[0];
#pragma unroll
    for (int w = 1; w < 8; w++) gmax = fmaxf(gmax, red[w]);
    __syncthreads();

    float lsum = 0.f;
    for (int i = tid; i < n; i += NTHREADS) {
        float e = __expf(buf[i] - gmax);
        buf[i] = e;
        lsum += e;
    }
#pragma unroll
    for (int off = 16; off; off >>= 1)
        lsum += __shfl_xor_sync(0xffffffffu, lsum, off);
    if (lane == 0) red[wid] = lsum;
    __syncthreads();
    float gsum = red[0];
#pragma unroll
    for (int w = 1; w < 8; w++) gsum += red[w];

    const float inv = 1.f / gsum;
    for (int i = tid; i < n; i += NTHREADS) row[i] = buf[i] * inv;
    for (int i = n + tid; i < SEQ; i += NTHREADS) row[i] = 0.f;
}

// ---------------------------------------------------------------------------
// Kernel 4: O = P @ V (NN GEMM, causal-truncated K extent).
// ---------------------------------------------------------------------------
__global__ void __launch_bounds__(NTHREADS, 2)
pv_kernel(float* __restrict__ out)
{
    __shared__ float As[2][BM * AS_STRIDE];
    __shared__ float Vs[2][BK * VS_STRIDE];

    const int b  = blockIdx.z;
    const int mt = blockIdx.y;
    const int e0 = blockIdx.x * BN;

    const float* P = g_p + (size_t)b * SEQ * SEQ;
    const float* V = g_qkv[2] + (size_t)b * SEQ * EMB;

    const int m0 = mt * BM;
    const int tid = threadIdx.x;
    const int warp = tid >> 5, lane = tid & 31;
    const int wm = warp & 1, wn = warp >> 1;
    const int g = lane >> 2, tig = lane & 3;

    // A loader: row tid>>2 (+64), f4 col tid&3
    const int ar = tid >> 2, ac = (tid & 3) * 4;
    const float* ag = P + (size_t)(m0 + ar) * SEQ + ac;
    const uint32_t asw = (uint32_t)__cvta_generic_to_shared(&As[0][0]) + (ar * AS_STRIDE + ac) * 4;
    // V loader: k = tid>>5 (+8), n4 = (tid&31)*4
    const int vk = tid >> 5, vn = (tid & 31) * 4;
    const float* vg = V + (size_t)vk * EMB + e0 + vn;
    const uint32_t vsw = (uint32_t)__cvta_generic_to_shared(&Vs[0][0]) + (vk * VS_STRIDE + vn) * 4;
    const uint32_t ABUF = BM * AS_STRIDE * 4;
    const uint32_t VBUF = BK * VS_STRIDE * 4;
    const uint32_t AROWS64 = 64 * AS_STRIDE * 4;
    const uint32_t VROWS8  = 8 * VS_STRIDE * 4;

    float acc[4][4][4];
#pragma unroll
    for (int i = 0; i < 4; i++)
#pragma unroll
        for (int j = 0; j < 4; j++)
#pragma unroll
            for (int k = 0; k < 4; k++) acc[i][j][k] = 0.f;

    cp16(asw, ag);              cp16(asw + AROWS64, ag + (size_t)64 * SEQ);
    cp16(vsw, vg);              cp16(vsw + VROWS8, vg + (size_t)8 * EMB);
    cp_commit();

    const int T = (mt + 1) * (BM / BK);
    for (int t = 0; t < T; ++t) {
        if (t + 1 < T) {
            const int nb = (t + 1) & 1;
            const float* a2 = ag + (t + 1) * BK;
            const float* v2 = vg + (size_t)(t + 1) * BK * EMB;
            cp16(asw + nb * ABUF, a2);          cp16(asw + nb * ABUF + AROWS64, a2 + (size_t)64 * SEQ);
            cp16(vsw + nb * VBUF, v2);          cp16(vsw + nb * VBUF + VROWS8, v2 + (size_t)8 * EMB);
            cp_commit();
            cp_wait<1>();
        } else {
            cp_wait<0>();
        }
        __syncthreads();

        const float* Ab = &As[t & 1][0];
        const float* Vb = &Vs[t & 1][0];
#pragma unroll
        for (int kk = 0; kk < 2; ++kk) {
            uint32_t a[4][4];
#pragma unroll
            for (int mi = 0; mi < 4; ++mi) {
                const float* p = Ab + (wm * 64 + mi * 16 + g) * AS_STRIDE + kk * 8 + tig;
                a[mi][0] = f2tf(p[0]);
                a[mi][2] = f2tf(p[4]);
                a[mi][1] = f2tf(p[8 * AS_STRIDE]);
                a[mi][3] = f2tf(p[8 * AS_STRIDE + 4]);
            }
#pragma unroll
            for (int ni = 0; ni < 4; ++ni) {
                const float* q = Vb + (kk * 8 + tig) * VS_STRIDE + wn * 32 + ni * 8 + g;
                uint32_t bf0 = f2tf(q[0]), bf1 = f2tf(q[4 * VS_STRIDE]);
#pragma unroll
                for (int mi = 0; mi < 4; ++mi) mma8(acc[mi][ni], a[mi], bf0, bf1);
            }
        }
        __syncthreads();
    }

#pragma unroll
    for (int mi = 0; mi < 4; ++mi) {
        const int row = m0 + wm * 64 + mi * 16 + g;
#pragma unroll
        for (int ni = 0; ni < 4; ++ni) {
            const int col = e0 + wn * 32 + ni * 8 + 2 * tig;
            float2 r0 = {acc[mi][ni][0], acc[mi][ni][1]};
            float2 r1 = {acc[mi][ni][2], acc[mi][ni][3]};
            *(float2*)(out + ((size_t)b * SEQ + row) * EMB + col)       = r0;
            *(float2*)(out + ((size_t)b * SEQ + row + 8) * EMB + col)   = r1;
        }
    }
}

// ---------------------------------------------------------------------------
extern "C" void kernel_launch(void* const* d_in, const int* in_sizes, int n_in,
                              void* d_out, int out_size)
{
    const float* xs = (const float*)d_in[0];
    const float* wq = (const float*)d_in[1];
    const float* bq = (const float*)d_in[2];
    const float* wk = (const float*)d_in[3];
    const float* bk = (const float*)d_in[4];
    const float* wv = (const float*)d_in[5];
    const float* bv = (const float*)d_in[6];
    float* out = (float*)d_out;

    dim3 gqkv(EMB / BN, (BATCH * SEQ) / BM, 3);          // (8, 64, 3)
    qkv_kernel<<<gqkv, NTHREADS>>>(xs, wq, bq, wk, bk, wv, bv);

    dim3 gsc(SEQ / BN, SEQ / BM, BATCH);                 // (16, 16, 4)
    scores_kernel<<<gsc, NTHREADS>>>();

    softmax_kernel<<<BATCH * SEQ, NTHREADS>>>();         // 8192 blocks

    dim3 gpv(EMB / BN, SEQ / BM, BATCH);                 // (8, 16, 4)
    pv_kernel<<<gpv, NTHREADS>>>(out);
}